// round 4
// baseline (speedup 1.0000x reference)
#include <cuda_runtime.h>
#include <cstdint>

#define BB 32
#define TT 8192
#define DD 256
#define UU 128

#define MT 128          // CTA row tile
#define KC 32           // K chunk
#define AST 36          // A smem row stride (floats), pad for conflict-free frags
#define BST 36          // B smem row stride

// Scratch (static device globals — allocation-free)
__device__ float g_hq[BB * UU];
__device__ float g_scores[BB * TT];
__device__ float g_partials[BB * 16 * DD];

// ---------------------------------------------------------------------------
// helpers
// ---------------------------------------------------------------------------
__device__ __forceinline__ uint32_t to_tf32(float x) {
    uint32_t r;
    asm("cvt.rna.tf32.f32 %0, %1;" : "=r"(r) : "f"(x));
    return r;
}

__device__ __forceinline__ void mma_tf32(float c[4],
                                         uint32_t a0, uint32_t a1, uint32_t a2, uint32_t a3,
                                         uint32_t b0, uint32_t b1) {
    asm volatile(
        "mma.sync.aligned.m16n8k8.row.col.f32.tf32.tf32.f32 "
        "{%0,%1,%2,%3}, {%4,%5,%6,%7}, {%8,%9}, {%0,%1,%2,%3};"
        : "+f"(c[0]), "+f"(c[1]), "+f"(c[2]), "+f"(c[3])
        : "r"(a0), "r"(a1), "r"(a2), "r"(a3), "r"(b0), "r"(b1));
}

// exact tanh via e^{2x}: tanh(x) = 1 - 2/(e^{2x}+1).  ~1e-6 abs error, handles +-inf.
__device__ __forceinline__ float tanh_acc(float x) {
    float e = __expf(2.0f * x);
    return 1.0f - __fdividef(2.0f, e + 1.0f);
}

// ---------------------------------------------------------------------------
// kernel 0: hq[b][u] = relu(query[b] @ W2[:,u] + W2b[u])
// ---------------------------------------------------------------------------
__global__ void hq_kernel(const float* __restrict__ query,
                          const float* __restrict__ W2,
                          const float* __restrict__ W2b) {
    int b = blockIdx.x;
    int u = threadIdx.x;
    const float* q = query + b * DD;
    float acc = 0.0f;
#pragma unroll 8
    for (int d = 0; d < DD; d++) acc += q[d] * W2[d * UU + u];
    acc += W2b[u];
    g_hq[b * UU + u] = fmaxf(acc, 0.0f);
}

// ---------------------------------------------------------------------------
// kernel 1: scores. CTA tile 128 rows x 128 units, tf32 mma, fused epilogue.
// ---------------------------------------------------------------------------
__global__ __launch_bounds__(256, 2) void scores_kernel(
    const float* __restrict__ values,
    const float* __restrict__ W1,
    const float* __restrict__ W1b,
    const float* __restrict__ Vk,
    const float* __restrict__ Vb) {
    __shared__ float As[MT * AST];   // [row][k]
    __shared__ float Bs[UU * BST];   // [n][k]  (W1 chunk transposed)
    __shared__ float s_hq[UU], s_b1[UU], s_v[UU];

    const int tid  = threadIdx.x;
    const int w    = tid >> 5;
    const int lane = tid & 31;
    const int g    = lane >> 2;
    const int tg   = lane & 3;
    const int row_base = blockIdx.x * MT;
    const int b = row_base >> 13;            // T = 8192, MT divides T

    if (tid < UU) {
        s_hq[tid] = g_hq[b * UU + tid];
        s_b1[tid] = W1b[tid];
        s_v[tid]  = Vk[tid];
    }

    float acc[16][4];
#pragma unroll
    for (int j = 0; j < 16; j++) {
        acc[j][0] = 0.f; acc[j][1] = 0.f; acc[j][2] = 0.f; acc[j][3] = 0.f;
    }

    for (int kc = 0; kc < DD / KC; kc++) {
        const int kb = kc * KC;
        // --- stage A tile: 128 rows x 32 k (float4, tf32-converted) ---
#pragma unroll
        for (int i = 0; i < 4; i++) {
            int idx = tid + i * 256;           // float4 index, 1024 total
            int r   = idx >> 3;
            int c4  = (idx & 7) * 4;
            float4 v = *reinterpret_cast<const float4*>(
                values + (row_base + r) * DD + kb + c4);
            uint4 t;
            t.x = to_tf32(v.x); t.y = to_tf32(v.y);
            t.z = to_tf32(v.z); t.w = to_tf32(v.w);
            *reinterpret_cast<uint4*>(As + r * AST + c4) = t;
        }
        // --- stage B tile transposed: Bs[n][k], 32 k x 128 n ---
#pragma unroll
        for (int i = 0; i < 16; i++) {
            int idx = tid + i * 256;           // 4096 total
            int n = idx & 127;
            int k = idx >> 7;
            float v = W1[(kb + k) * UU + n];
            *reinterpret_cast<uint32_t*>(Bs + n * BST + k) = to_tf32(v);
        }
        __syncthreads();

#pragma unroll
        for (int ks = 0; ks < 4; ks++) {
            const int k0 = ks * 8;
            const float* ap = As + (16 * w + g) * AST + k0 + tg;
            uint32_t a0 = __float_as_uint(ap[0]);
            uint32_t a1 = __float_as_uint(ap[8 * AST]);
            uint32_t a2 = __float_as_uint(ap[4]);
            uint32_t a3 = __float_as_uint(ap[8 * AST + 4]);
#pragma unroll
            for (int j = 0; j < 16; j++) {
                const float* bp = Bs + (8 * j + g) * BST + k0 + tg;
                uint32_t b0 = __float_as_uint(bp[0]);
                uint32_t b1 = __float_as_uint(bp[4]);
                mma_tf32(acc[j], a0, a1, a2, a3, b0, b1);
            }
        }
        __syncthreads();
    }

    // --- epilogue: score = sum_u V[u]*tanh(relu(acc+b1)+hq) , + Vb ---
    float sg = 0.f, sg8 = 0.f;
#pragma unroll
    for (int j = 0; j < 16; j++) {
        int c0 = 8 * j + 2 * tg;
        int c1 = c0 + 1;
        float v0 = s_v[c0], v1 = s_v[c1];
        float h0 = s_hq[c0], h1 = s_hq[c1];
        float b0 = s_b1[c0], b1f = s_b1[c1];
        sg  += v0 * tanh_acc(fmaxf(acc[j][0] + b0, 0.f) + h0);
        sg  += v1 * tanh_acc(fmaxf(acc[j][1] + b1f, 0.f) + h1);
        sg8 += v0 * tanh_acc(fmaxf(acc[j][2] + b0, 0.f) + h0);
        sg8 += v1 * tanh_acc(fmaxf(acc[j][3] + b1f, 0.f) + h1);
    }
    // reduce over the quad (tg = 0..3)
    sg  += __shfl_xor_sync(0xffffffffu, sg, 1);
    sg  += __shfl_xor_sync(0xffffffffu, sg, 2);
    sg8 += __shfl_xor_sync(0xffffffffu, sg8, 1);
    sg8 += __shfl_xor_sync(0xffffffffu, sg8, 2);
    if (tg == 0) {
        float vb = Vb[0];
        g_scores[row_base + 16 * w + g]     = sg + vb;
        g_scores[row_base + 16 * w + g + 8] = sg8 + vb;
    }
}

// ---------------------------------------------------------------------------
// kernel 2: softmax over T per batch, writes normalized weights to d_out
// ---------------------------------------------------------------------------
__global__ void softmax_kernel(float* __restrict__ w_out) {
    __shared__ float red[8];
    const int b = blockIdx.x;
    const int tid = threadIdx.x;
    const float* s = g_scores + b * TT;
    float* wo = w_out + b * TT;

    float m = -3.4e38f;
    for (int t = tid; t < TT; t += 256) m = fmaxf(m, s[t]);
#pragma unroll
    for (int o = 16; o > 0; o >>= 1) m = fmaxf(m, __shfl_xor_sync(0xffffffffu, m, o));
    if ((tid & 31) == 0) red[tid >> 5] = m;
    __syncthreads();
    float mx = red[0];
#pragma unroll
    for (int i = 1; i < 8; i++) mx = fmaxf(mx, red[i]);
    __syncthreads();

    float sum = 0.f;
    for (int t = tid; t < TT; t += 256) {
        float e = __expf(s[t] - mx);
        wo[t] = e;
        sum += e;
    }
#pragma unroll
    for (int o = 16; o > 0; o >>= 1) sum += __shfl_xor_sync(0xffffffffu, sum, o);
    if ((tid & 31) == 0) red[tid >> 5] = sum;
    __syncthreads();
    float tot = 0.f;
#pragma unroll
    for (int i = 0; i < 8; i++) tot += red[i];
    float inv = 1.0f / tot;
    for (int t = tid; t < TT; t += 256) wo[t] *= inv;
}

// ---------------------------------------------------------------------------
// kernel 3: context partials: 512 blocks, each (b, chunk of 512 t-rows)
// ---------------------------------------------------------------------------
__global__ __launch_bounds__(256) void ctx_partial_kernel(
    const float* __restrict__ values, const float* __restrict__ wts) {
    __shared__ float ws[512];
    const int bid = blockIdx.x;          // 0..511
    const int b = bid >> 4;
    const int t0 = (bid & 15) * 512;
    const int d = threadIdx.x;

    for (int i = threadIdx.x; i < 512; i += 256) ws[i] = wts[b * TT + t0 + i];
    __syncthreads();

    const float* vp = values + (b * TT + t0) * DD + d;
    float acc = 0.f;
#pragma unroll 8
    for (int i = 0; i < 512; i++) acc += ws[i] * vp[i * DD];
    g_partials[bid * DD + d] = acc;
}

// ---------------------------------------------------------------------------
// kernel 4: final context reduction -> d_out[0 : B*D]
// ---------------------------------------------------------------------------
__global__ void ctx_final_kernel(float* __restrict__ ctx) {
    const int b = blockIdx.x;
    const int d = threadIdx.x;
    float acc = 0.f;
#pragma unroll
    for (int c = 0; c < 16; c++) acc += g_partials[(b * 16 + c) * DD + d];
    ctx[b * DD + d] = acc;
}

// ---------------------------------------------------------------------------
extern "C" void kernel_launch(void* const* d_in, const int* in_sizes, int n_in,
                              void* d_out, int out_size) {
    const float* query = (const float*)d_in[0];
    const float* values = (const float*)d_in[1];
    const float* W1 = (const float*)d_in[2];
    const float* W1b = (const float*)d_in[3];
    const float* W2 = (const float*)d_in[4];
    const float* W2b = (const float*)d_in[5];
    const float* Vk = (const float*)d_in[6];
    const float* Vb = (const float*)d_in[7];

    float* out = (float*)d_out;
    float* ctx = out;              // [B, D]
    float* wts = out + BB * DD;    // [B, T, 1]

    hq_kernel<<<BB, UU>>>(query, W2, W2b);
    scores_kernel<<<(BB * TT) / MT, 256>>>(values, W1, W1b, Vk, Vb);
    softmax_kernel<<<BB, 256>>>(wts);
    ctx_partial_kernel<<<BB * 16, 256>>>(values, wts);
    ctx_final_kernel<<<BB, DD>>>(ctx);
}

// round 6
// speedup vs baseline: 1.8199x; 1.8199x over previous
#include <cuda_runtime.h>
#include <cstdint>

#define BB 32
#define TT 8192
#define DD 256
#define UU 128
#define MT 256
#define NCTA ((BB * TT) / MT)   // 1024 CTAs, 32 per batch

// ---- dynamic SMEM layout (bytes) ----
#define A_OFF   0        // 2 x (256 rows x 128B, swizzled)   = 65536
#define B_OFF   65536    // 2 x (128 rows x 128B, swizzled)   = 32768
#define SC_OFF  98304    // [2][256] floats (per-col-half row scores) = 2048
#define ES_OFF  100352   // 256 floats (local exp weights)
#define HQ_OFF  101376   // 128 floats
#define B1_OFF  101888   // 128 floats
#define VV_OFF  102400   // 128 floats
#define RED_OFF 102912   // reduction scratch
#define PC_OFF  103168   // [2][256] ctx partials
#define SMEM_BYTES 105472

// ---- scratch globals (allocation-free) ----
__device__ float g_hq[BB * UU];
__device__ float g_W1t[UU * DD];        // W1 transposed, tf32(rna)-rounded
__device__ float g_scores[BB * TT];
__device__ float g_stats[NCTA * 2];     // per-CTA (local max, local expsum)
__device__ float g_pctx[NCTA * DD];     // per-CTA unnormalized partial context
__device__ float g_bstats[BB * 2];      // per-batch (global max, 1/sum)

// ---------------------------------------------------------------------------
// helpers
// ---------------------------------------------------------------------------
__device__ __forceinline__ uint32_t smem_u32(const void* p) {
    uint32_t a;
    asm("{ .reg .u64 t; cvta.to.shared.u64 t, %1; cvt.u32.u64 %0, t; }" : "=r"(a) : "l"(p));
    return a;
}
__device__ __forceinline__ uint32_t swz(uint32_t off) {   // 128B XOR swizzle
    return off ^ ((off >> 3) & 0x70);
}
__device__ __forceinline__ void ldsm4(uint32_t (&r)[4], uint32_t addr) {
    asm volatile("ldmatrix.sync.aligned.m8n8.x4.shared.b16 {%0,%1,%2,%3}, [%4];"
                 : "=r"(r[0]), "=r"(r[1]), "=r"(r[2]), "=r"(r[3]) : "r"(addr));
}
__device__ __forceinline__ void mma_tf32(float c[4],
                                         uint32_t a0, uint32_t a1, uint32_t a2, uint32_t a3,
                                         uint32_t b0, uint32_t b1) {
    asm volatile(
        "mma.sync.aligned.m16n8k8.row.col.f32.tf32.tf32.f32 "
        "{%0,%1,%2,%3}, {%4,%5,%6,%7}, {%8,%9}, {%0,%1,%2,%3};"
        : "+f"(c[0]), "+f"(c[1]), "+f"(c[2]), "+f"(c[3])
        : "r"(a0), "r"(a1), "r"(a2), "r"(a3), "r"(b0), "r"(b1));
}
__device__ __forceinline__ void cp16(uint32_t dst, const void* src) {
    asm volatile("cp.async.cg.shared.global [%0], [%1], 16;"
                 :: "r"(dst), "l"(src) : "memory");
}
__device__ __forceinline__ void cp_commit() {
    asm volatile("cp.async.commit_group;" ::: "memory");
}
__device__ __forceinline__ void cp_wait1() {
    asm volatile("cp.async.wait_group 1;" ::: "memory");
}
__device__ __forceinline__ float tanh_acc(float x) {   // 2 MUFU, ~1e-6 abs err
    float e = __expf(2.0f * x);
    return 1.0f - __fdividef(2.0f, e + 1.0f);
}

// ---------------------------------------------------------------------------
// prep kernels
// ---------------------------------------------------------------------------
__global__ void hq_kernel(const float* __restrict__ query,
                          const float* __restrict__ W2,
                          const float* __restrict__ W2b) {
    int b = blockIdx.x, u = threadIdx.x;
    const float* q = query + b * DD;
    float acc = 0.0f;
#pragma unroll 8
    for (int d = 0; d < DD; d++) acc += q[d] * W2[d * UU + u];
    g_hq[b * UU + u] = fmaxf(acc + W2b[u], 0.0f);
}

__global__ void prep_kernel(const float* __restrict__ W1) {
    int u = blockIdx.x, d = threadIdx.x;
    float v = W1[d * UU + u];
    uint32_t t;
    asm("cvt.rna.tf32.f32 %0, %1;" : "=r"(t) : "f"(v));
    g_W1t[u * DD + d] = __uint_as_float(t);
}

// ---------------------------------------------------------------------------
// fused: scores (tf32 mma + ldmatrix + cp.async pipeline) + local softmax
//        + partial context.  512 threads, 16 warps; warp = (rg, ch):
//        rows [32*rg, 32*rg+32) x cols [64*ch, 64*ch+64).
// ---------------------------------------------------------------------------
__global__ __launch_bounds__(512, 1)
void scores_kernel(const float* __restrict__ values,
                   const float* __restrict__ W1b,
                   const float* __restrict__ Vk,
                   const float* __restrict__ Vb) {
    extern __shared__ char smem[];
    const uint32_t sbase = smem_u32(smem);
    const int tid  = threadIdx.x;
    const int wid  = tid >> 5;
    const int lane = tid & 31;
    const int rg   = wid >> 1;        // row group 0..7
    const int ch   = wid & 1;         // col half 0..1
    const int mrow = lane & 7;
    const int mi   = lane >> 3;
    const int tg   = lane & 3;
    const int g    = lane >> 2;
    const int row0 = blockIdx.x * MT;
    const int b    = blockIdx.x >> 5; // 32 CTAs per batch

    float* s_sc = (float*)(smem + SC_OFF);
    float* s_es = (float*)(smem + ES_OFF);
    float* s_hq = (float*)(smem + HQ_OFF);
    float* s_b1 = (float*)(smem + B1_OFF);
    float* s_v  = (float*)(smem + VV_OFF);
    float* s_rd = (float*)(smem + RED_OFF);
    float* s_pc = (float*)(smem + PC_OFF);

    if (tid < UU) {
        s_hq[tid] = g_hq[b * UU + tid];
        s_b1[tid] = W1b[tid];
        s_v[tid]  = Vk[tid];
    }

    // ---- cp.async staging ----
    auto stageA = [&](int c, int buf) {
        const float* src0 = values + (size_t)row0 * DD + c * 32;
#pragma unroll
        for (int i = 0; i < 4; i++) {
            int idx = tid + i * 512;           // 2048 x 16B = 256 rows x 32 floats
            int r = idx >> 3, cc = idx & 7;
            cp16(sbase + A_OFF + buf * 32768 + swz(r * 128 + cc * 16),
                 src0 + (size_t)r * DD + cc * 4);
        }
    };
    auto stageB = [&](int c, int buf) {
        const float* src0 = g_W1t + c * 32;
#pragma unroll
        for (int i = 0; i < 2; i++) {
            int idx = tid + i * 512;           // 1024 x 16B = 128 rows x 32 floats
            int u = idx >> 3, cc = idx & 7;
            cp16(sbase + B_OFF + buf * 16384 + swz(u * 128 + cc * 16),
                 src0 + u * DD + cc * 4);
        }
    };

    stageA(0, 0); stageB(0, 0); cp_commit();
    stageA(1, 1); stageB(1, 1); cp_commit();

    float acc[2][8][4];
#pragma unroll
    for (int m = 0; m < 2; m++)
#pragma unroll
        for (int j = 0; j < 8; j++)
#pragma unroll
            for (int q = 0; q < 4; q++) acc[m][j][q] = 0.0f;

    // A lane address components (constant over chunks except k)
    const int a_row0 = 32 * rg + mrow + (mi & 1) * 8;
    const int a_koff = (mi >> 1) * 16;
    const int b_row  = 64 * ch + (mi >> 1) * 8 + mrow;
    const int b_koff = (mi & 1) * 16;

    for (int c = 0; c < 8; c++) {
        const int buf = c & 1;
        cp_wait1();
        __syncthreads();

        const uint32_t abase = sbase + A_OFF + buf * 32768;
        const uint32_t bbase = sbase + B_OFF + buf * 16384;
#pragma unroll
        for (int ks = 0; ks < 4; ks++) {
            const int k0 = ks * 32;            // bytes
            uint32_t a0[4], a1[4];
            ldsm4(a0, abase + swz(a_row0 * 128 + a_koff + k0));
            ldsm4(a1, abase + swz((a_row0 + 16) * 128 + a_koff + k0));
#pragma unroll
            for (int t = 0; t < 4; t++) {
                uint32_t bq[4];
                ldsm4(bq, bbase + swz((b_row + 16 * t) * 128 + b_koff + k0));
                mma_tf32(acc[0][2 * t],     a0[0], a0[1], a0[2], a0[3], bq[0], bq[1]);
                mma_tf32(acc[0][2 * t + 1], a0[0], a0[1], a0[2], a0[3], bq[2], bq[3]);
                mma_tf32(acc[1][2 * t],     a1[0], a1[1], a1[2], a1[3], bq[0], bq[1]);
                mma_tf32(acc[1][2 * t + 1], a1[0], a1[1], a1[2], a1[3], bq[2], bq[3]);
            }
        }
        __syncthreads();
        if (c + 2 < 8) { stageA(c + 2, buf); stageB(c + 2, buf); }
        cp_commit();
    }

    // ---- epilogue 1: per-row score partials (this warp's 64-col half) ----
    float s[4] = {0.f, 0.f, 0.f, 0.f};
#pragma unroll
    for (int j = 0; j < 8; j++) {
        const int u0 = 64 * ch + 8 * j + 2 * tg;
        const int u1 = u0 + 1;
        const float v0 = s_v[u0], v1 = s_v[u1];
        const float h0 = s_hq[u0], h1 = s_hq[u1];
        const float c0 = s_b1[u0], c1 = s_b1[u1];
#pragma unroll
        for (int m = 0; m < 2; m++) {
            s[2 * m]     += v0 * tanh_acc(fmaxf(acc[m][j][0] + c0, 0.f) + h0)
                          + v1 * tanh_acc(fmaxf(acc[m][j][1] + c1, 0.f) + h1);
            s[2 * m + 1] += v0 * tanh_acc(fmaxf(acc[m][j][2] + c0, 0.f) + h0)
                          + v1 * tanh_acc(fmaxf(acc[m][j][3] + c1, 0.f) + h1);
        }
    }
#pragma unroll
    for (int i = 0; i < 4; i++) {
        s[i] += __shfl_xor_sync(0xffffffffu, s[i], 1);
        s[i] += __shfl_xor_sync(0xffffffffu, s[i], 2);
    }
    if (tg == 0) {
        const int rb = 32 * rg + g;
        s_sc[ch * 256 + rb]      = s[0];
        s_sc[ch * 256 + rb + 8]  = s[1];
        s_sc[ch * 256 + rb + 16] = s[2];
        s_sc[ch * 256 + rb + 24] = s[3];
    }
    __syncthreads();

    // ---- epilogue 2: combine col-halves, local max / exp / sum ----
    float myv = -3.0e38f;
    if (tid < 256) {
        myv = s_sc[tid] + s_sc[256 + tid] + Vb[0];
        g_scores[row0 + tid] = myv;
    }
    float m = myv;
#pragma unroll
    for (int o = 16; o > 0; o >>= 1) m = fmaxf(m, __shfl_xor_sync(0xffffffffu, m, o));
    if (lane == 0) s_rd[wid] = m;
    __syncthreads();
    if (tid == 0) {
        float mx = s_rd[0];
#pragma unroll
        for (int i = 1; i < 16; i++) mx = fmaxf(mx, s_rd[i]);
        s_rd[32] = mx;
    }
    __syncthreads();
    const float mloc = s_rd[32];
    float e = (tid < 256) ? __expf(myv - mloc) : 0.0f;
    if (tid < 256) s_es[tid] = e;
    float sum = e;
#pragma unroll
    for (int o = 16; o > 0; o >>= 1) sum += __shfl_xor_sync(0xffffffffu, sum, o);
    if (lane == 0) s_rd[16 + wid] = sum;
    __syncthreads();
    if (tid == 0) {
        float tot = 0.0f;
#pragma unroll
        for (int i = 0; i < 16; i++) tot += s_rd[16 + i];
        g_stats[blockIdx.x * 2]     = mloc;
        g_stats[blockIdx.x * 2 + 1] = tot;
    }

    // ---- epilogue 3: partial context (values tile is L2-hot) ----
    {
        const int half = tid >> 8, d = tid & 255;
        const float* vp = values + ((size_t)row0 + half * 128) * DD + d;
        const float* ep = s_es + half * 128;
        float a = 0.0f;
#pragma unroll 8
        for (int r = 0; r < 128; r++) a += ep[r] * vp[(size_t)r * DD];
        s_pc[half * 256 + d] = a;
    }
    __syncthreads();
    if (tid < 256) g_pctx[blockIdx.x * DD + tid] = s_pc[tid] + s_pc[256 + tid];
}

// ---------------------------------------------------------------------------
// per-batch rescale + context reduction
// ---------------------------------------------------------------------------
__global__ void reduce_kernel(float* __restrict__ ctx) {
    __shared__ float cm[32], cs[32], coef[32], sInv;
    const int b = blockIdx.x, tid = threadIdx.x;
    if (tid < 32) {
        cm[tid] = g_stats[(b * 32 + tid) * 2];
        cs[tid] = g_stats[(b * 32 + tid) * 2 + 1];
    }
    __syncthreads();
    if (tid == 0) {
        float M = cm[0];
#pragma unroll
        for (int i = 1; i < 32; i++) M = fmaxf(M, cm[i]);
        float S = 0.0f;
#pragma unroll
        for (int i = 0; i < 32; i++) { float c = __expf(cm[i] - M); coef[i] = c; S += c * cs[i]; }
        sInv = 1.0f / S;
        g_bstats[b * 2] = M;
        g_bstats[b * 2 + 1] = 1.0f / S;
    }
    __syncthreads();
    float acc = 0.0f;
#pragma unroll
    for (int c = 0; c < 32; c++) acc += coef[c] * g_pctx[(b * 32 + c) * DD + tid];
    ctx[b * DD + tid] = acc * sInv;
}

// normalized attention weights
__global__ void weights_kernel(float* __restrict__ w) {
    int i = blockIdx.x * 256 + threadIdx.x;
    int b = i >> 13;
    w[i] = __expf(g_scores[i] - g_bstats[b * 2]) * g_bstats[b * 2 + 1];
}

// ---------------------------------------------------------------------------
extern "C" void kernel_launch(void* const* d_in, const int* in_sizes, int n_in,
                              void* d_out, int out_size) {
    const float* query  = (const float*)d_in[0];
    const float* values = (const float*)d_in[1];
    const float* W1     = (const float*)d_in[2];
    const float* W1b    = (const float*)d_in[3];
    const float* W2     = (const float*)d_in[4];
    const float* W2b    = (const float*)d_in[5];
    const float* Vk     = (const float*)d_in[6];
    const float* Vb     = (const float*)d_in[7];

    float* out = (float*)d_out;
    float* ctx = out;               // [B, D]
    float* wts = out + BB * DD;     // [B, T, 1]

    static bool attr_set = false;
    if (!attr_set) {
        cudaFuncSetAttribute(scores_kernel, cudaFuncAttributeMaxDynamicSharedMemorySize,
                             SMEM_BYTES);
        attr_set = true;
    }

    hq_kernel<<<BB, UU>>>(query, W2, W2b);
    prep_kernel<<<UU, DD>>>(W1);
    scores_kernel<<<NCTA, 512, SMEM_BYTES>>>(values, W1b, Vk, Vb);
    reduce_kernel<<<BB, DD>>>(ctx);
    weights_kernel<<<(BB * TT) / 256, 256>>>(wts);
}

// round 8
// speedup vs baseline: 2.0990x; 1.1534x over previous
#include <cuda_runtime.h>
#include <cuda_fp16.h>
#include <cstdint>

#define BB 32
#define TT 8192
#define DD 256
#define UU 128
#define MT 128
#define NCTA ((BB * TT) / MT)   // 2048 CTAs, 64 per batch

// ---- dynamic SMEM layout (bytes). rows padded to 80B (conflict-free LDSM) ----
#define A_OFF   0        // 2 x (128 rows x 80B)  = 20480
#define B_OFF   20480    // 4 x (128 rows x 80B)  = 40960
#define SC_OFF  61440    // [2][128] floats
#define ES_OFF  62464    // 128 floats
#define HQ_OFF  62976    // 128 floats
#define B1_OFF  63488    // 128 floats
#define VV_OFF  64000    // 128 floats
#define RED_OFF 64512    // 64 floats
#define SMEM_BYTES 64768

// ---- scratch globals (allocation-free) ----
__device__ float  g_hq[BB * UU];
__device__ __half g_W1h[UU * DD];       // W1 transposed -> [u][d], fp16
__device__ float  g_scores[BB * TT];
__device__ float  g_stats[NCTA * 2];    // per-CTA (local max, local expsum)
__device__ float  g_pctx[NCTA * DD];    // per-CTA unnormalized partial context
__device__ float  g_bstats[BB * 2];     // per-batch (global max, 1/sum)

// ---------------------------------------------------------------------------
// helpers
// ---------------------------------------------------------------------------
__device__ __forceinline__ uint32_t smem_u32(const void* p) {
    uint32_t a;
    asm("{ .reg .u64 t; cvta.to.shared.u64 t, %1; cvt.u32.u64 %0, t; }" : "=r"(a) : "l"(p));
    return a;
}
__device__ __forceinline__ void ldsm4(uint32_t (&r)[4], uint32_t addr) {
    asm volatile("ldmatrix.sync.aligned.m8n8.x4.shared.b16 {%0,%1,%2,%3}, [%4];"
                 : "=r"(r[0]), "=r"(r[1]), "=r"(r[2]), "=r"(r[3]) : "r"(addr));
}
__device__ __forceinline__ void mma_f16(float c[4],
                                        uint32_t a0, uint32_t a1, uint32_t a2, uint32_t a3,
                                        uint32_t b0, uint32_t b1) {
    asm volatile(
        "mma.sync.aligned.m16n8k16.row.col.f32.f16.f16.f32 "
        "{%0,%1,%2,%3}, {%4,%5,%6,%7}, {%8,%9}, {%0,%1,%2,%3};"
        : "+f"(c[0]), "+f"(c[1]), "+f"(c[2]), "+f"(c[3])
        : "r"(a0), "r"(a1), "r"(a2), "r"(a3), "r"(b0), "r"(b1));
}
__device__ __forceinline__ void cp16(uint32_t dst, const void* src) {
    asm volatile("cp.async.cg.shared.global [%0], [%1], 16;"
                 :: "r"(dst), "l"(src) : "memory");
}
__device__ __forceinline__ void cp_commit() {
    asm volatile("cp.async.commit_group;" ::: "memory");
}
__device__ __forceinline__ void cp_wait2() {
    asm volatile("cp.async.wait_group 2;" ::: "memory");
}
__device__ __forceinline__ uint32_t h2_bits(__half2 h) {
    union { __half2 h; uint32_t u; } cvt;
    cvt.h = h;
    return cvt.u;
}
__device__ __forceinline__ float tanh_acc(float x) {   // ~1e-6 abs err
    float e = __expf(2.0f * x);
    return 1.0f - __fdividef(2.0f, e + 1.0f);
}

// ---------------------------------------------------------------------------
// prep kernels
// ---------------------------------------------------------------------------
__global__ void hq_kernel(const float* __restrict__ query,
                          const float* __restrict__ W2,
                          const float* __restrict__ W2b) {
    int b = blockIdx.x, u = threadIdx.x;
    const float* q = query + b * DD;
    float acc = 0.0f;
#pragma unroll 8
    for (int d = 0; d < DD; d++) acc += q[d] * W2[d * UU + u];
    g_hq[b * UU + u] = fmaxf(acc + W2b[u], 0.0f);
}

__global__ void prep_kernel(const float* __restrict__ W1) {
    int u = blockIdx.x, d = threadIdx.x;
    g_W1h[u * DD + d] = __float2half_rn(W1[d * UU + u]);
}

// ---------------------------------------------------------------------------
// fused: scores (fp16 mma, reg-pipelined A, cp.async ring B) + local softmax
//        + partial context.  256 threads, 8 warps; warp = (rg 0..3, ch 0..1):
//        rows [32*rg, +32) x cols [64*ch, +64).
// ---------------------------------------------------------------------------
__global__ __launch_bounds__(256, 2)
void scores_kernel(const float* __restrict__ values,
                   const float* __restrict__ W1b,
                   const float* __restrict__ Vk,
                   const float* __restrict__ Vb) {
    extern __shared__ char smem[];
    const uint32_t sbase = smem_u32(smem);
    const int tid  = threadIdx.x;
    const int wid  = tid >> 5;
    const int lane = tid & 31;
    const int rg   = wid >> 1;
    const int ch   = wid & 1;
    const int mrow = lane & 7;
    const int mi   = lane >> 3;
    const int tg   = lane & 3;
    const int g    = lane >> 2;
    const int row0 = blockIdx.x * MT;
    const int b    = blockIdx.x >> 6;   // 64 CTAs per batch

    float* s_sc = (float*)(smem + SC_OFF);
    float* s_es = (float*)(smem + ES_OFF);
    float* s_hq = (float*)(smem + HQ_OFF);
    float* s_b1 = (float*)(smem + B1_OFF);
    float* s_v  = (float*)(smem + VV_OFF);
    float* s_rd = (float*)(smem + RED_OFF);

    if (tid < UU) {
        s_hq[tid] = g_hq[b * UU + tid];
        s_b1[tid] = W1b[tid];
        s_v[tid]  = Vk[tid];
    }

    // ---- B staging via cp.async (fp16, 4-buffer ring) ----
    auto stageB = [&](int c) {
        const uint32_t base = sbase + B_OFF + (c & 3) * 10240;
        const __half* src0 = g_W1h + c * 32;
#pragma unroll
        for (int i = 0; i < 2; i++) {
            int idx = tid + i * 256;         // 512 x 16B = 128 rows x 32 halves
            int u = idx >> 2, kk = idx & 3;
            cp16(base + u * 80 + kk * 16, src0 + u * DD + kk * 8);
        }
    };

    // ---- A staging: LDG fp32 -> regs -> cvt -> STS fp16 ----
    const int ar  = tid >> 3;                // base row handled by this thread
    const int ac4 = tid & 7;                 // float4 column
    float4 av[4];
    auto ldgA = [&](int c) {
        const float* src0 = values + (size_t)row0 * DD + c * 32 + ac4 * 4;
#pragma unroll
        for (int i = 0; i < 4; i++)
            av[i] = *(const float4*)(src0 + (size_t)(ar + i * 32) * DD);
    };
    auto stsA = [&](int buf) {
#pragma unroll
        for (int i = 0; i < 4; i++) {
            __half2 h0 = __floats2half2_rn(av[i].x, av[i].y);
            __half2 h1 = __floats2half2_rn(av[i].z, av[i].w);
            uint2 u2 = make_uint2(h2_bits(h0), h2_bits(h1));
            *(uint2*)(smem + A_OFF + buf * 10240 + (ar + i * 32) * 80 + ac4 * 8) = u2;
        }
    };

    stageB(0); cp_commit();
    stageB(1); cp_commit();
    stageB(2); cp_commit();
    ldgA(0);
    stsA(0);
    ldgA(1);
    cp_wait2();
    __syncthreads();

    float acc[2][8][4];
#pragma unroll
    for (int m = 0; m < 2; m++)
#pragma unroll
        for (int j = 0; j < 8; j++)
#pragma unroll
            for (int q = 0; q < 4; q++) acc[m][j][q] = 0.0f;

    // fragment address components
    const int a_r  = 32 * rg + mrow + 8 * (mi & 1);
    const int a_kb = (mi >> 1) * 16;
    const int b_n  = 64 * ch + mrow + 8 * (mi >> 1);
    const int b_kb = (mi & 1) * 16;

    for (int c = 0; c < 8; c++) {
        const uint32_t abase = sbase + A_OFF + (c & 1) * 10240;
        const uint32_t bbase = sbase + B_OFF + (c & 3) * 10240;
#pragma unroll
        for (int ks = 0; ks < 2; ks++) {
            const int k0 = ks * 32;          // bytes within 64B row payload
            uint32_t a0[4], a1[4];
            ldsm4(a0, abase + (a_r)      * 80 + a_kb + k0);
            ldsm4(a1, abase + (a_r + 16) * 80 + a_kb + k0);
#pragma unroll
            for (int nt = 0; nt < 4; nt++) {
                uint32_t bq[4];
                ldsm4(bq, bbase + (b_n + 16 * nt) * 80 + b_kb + k0);
                mma_f16(acc[0][2 * nt],     a0[0], a0[1], a0[2], a0[3], bq[0], bq[1]);
                mma_f16(acc[0][2 * nt + 1], a0[0], a0[1], a0[2], a0[3], bq[2], bq[3]);
                mma_f16(acc[1][2 * nt],     a1[0], a1[1], a1[2], a1[3], bq[0], bq[1]);
                mma_f16(acc[1][2 * nt + 1], a1[0], a1[1], a1[2], a1[3], bq[2], bq[3]);
            }
        }
        if (c + 1 < 8) stsA((c + 1) & 1);
        if (c + 2 < 8) ldgA(c + 2);
        if (c + 3 < 8) stageB(c + 3);
        cp_commit();
        cp_wait2();
        __syncthreads();
    }

    // ---- epilogue 1: per-row score partials (this warp's 64-col half) ----
    float s[4] = {0.f, 0.f, 0.f, 0.f};
#pragma unroll
    for (int j = 0; j < 8; j++) {
        const int u0 = 64 * ch + 8 * j + 2 * tg;
        const int u1 = u0 + 1;
        const float v0 = s_v[u0], v1 = s_v[u1];
        const float h0 = s_hq[u0], h1 = s_hq[u1];
        const float c0 = s_b1[u0], c1 = s_b1[u1];
#pragma unroll
        for (int m = 0; m < 2; m++) {
            s[2 * m]     += v0 * tanh_acc(fmaxf(acc[m][j][0] + c0, 0.f) + h0)
                          + v1 * tanh_acc(fmaxf(acc[m][j][1] + c1, 0.f) + h1);
            s[2 * m + 1] += v0 * tanh_acc(fmaxf(acc[m][j][2] + c0, 0.f) + h0)
                          + v1 * tanh_acc(fmaxf(acc[m][j][3] + c1, 0.f) + h1);
        }
    }
#pragma unroll
    for (int i = 0; i < 4; i++) {
        s[i] += __shfl_xor_sync(0xffffffffu, s[i], 1);
        s[i] += __shfl_xor_sync(0xffffffffu, s[i], 2);
    }
    if (tg == 0) {
        const int rb = 32 * rg + g;
        s_sc[ch * 128 + rb]      = s[0];
        s_sc[ch * 128 + rb + 8]  = s[1];
        s_sc[ch * 128 + rb + 16] = s[2];
        s_sc[ch * 128 + rb + 24] = s[3];
    }
    __syncthreads();

    // ---- epilogue 2: combine halves, local max / exp / sum ----
    float myv = -3.0e38f;
    if (tid < 128) {
        myv = s_sc[tid] + s_sc[128 + tid] + Vb[0];
        g_scores[row0 + tid] = myv;
    }
    float m = myv;
#pragma unroll
    for (int o = 16; o > 0; o >>= 1) m = fmaxf(m, __shfl_xor_sync(0xffffffffu, m, o));
    if (lane == 0 && wid < 4) s_rd[wid] = m;
    __syncthreads();
    if (tid == 0) {
        float mx = fmaxf(fmaxf(s_rd[0], s_rd[1]), fmaxf(s_rd[2], s_rd[3]));
        s_rd[32] = mx;
    }
    __syncthreads();
    const float mloc = s_rd[32];
    float e = (tid < 128) ? __expf(myv - mloc) : 0.0f;
    if (tid < 128) s_es[tid] = e;
    float sum = e;
#pragma unroll
    for (int o = 16; o > 0; o >>= 1) sum += __shfl_xor_sync(0xffffffffu, sum, o);
    if (lane == 0 && wid < 4) s_rd[8 + wid] = sum;
    __syncthreads();
    if (tid == 0) {
        g_stats[blockIdx.x * 2]     = mloc;
        g_stats[blockIdx.x * 2 + 1] = s_rd[8] + s_rd[9] + s_rd[10] + s_rd[11];
    }

    // ---- epilogue 3: partial context (tile is L2-hot; exact fp32) ----
    {
        const float* vp = values + (size_t)row0 * DD + tid;
        float a = 0.0f;
#pragma unroll 8
        for (int r = 0; r < MT; r++) a += s_es[r] * vp[(size_t)r * DD];
        g_pctx[blockIdx.x * DD + tid] = a;
    }
}

// ---------------------------------------------------------------------------
// per-batch rescale + context reduction (64 partials per batch)
// ---------------------------------------------------------------------------
__global__ void reduce_kernel(float* __restrict__ ctx) {
    __shared__ float cm[64], cs[64], coef[64], sInv;
    const int b = blockIdx.x, tid = threadIdx.x;
    if (tid < 64) {
        cm[tid] = g_stats[(b * 64 + tid) * 2];
        cs[tid] = g_stats[(b * 64 + tid) * 2 + 1];
    }
    __syncthreads();
    if (tid == 0) {
        float M = cm[0];
#pragma unroll
        for (int i = 1; i < 64; i++) M = fmaxf(M, cm[i]);
        float S = 0.0f;
#pragma unroll
        for (int i = 0; i < 64; i++) { float c = __expf(cm[i] - M); coef[i] = c; S += c * cs[i]; }
        sInv = 1.0f / S;
        g_bstats[b * 2] = M;
        g_bstats[b * 2 + 1] = 1.0f / S;
    }
    __syncthreads();
    float acc = 0.0f;
#pragma unroll
    for (int c = 0; c < 64; c++) acc += coef[c] * g_pctx[(b * 64 + c) * DD + tid];
    ctx[b * DD + tid] = acc * sInv;
}

// normalized attention weights
__global__ void weights_kernel(float* __restrict__ w) {
    int i = blockIdx.x * 256 + threadIdx.x;
    int b = i >> 13;
    w[i] = __expf(g_scores[i] - g_bstats[b * 2]) * g_bstats[b * 2 + 1];
}

// ---------------------------------------------------------------------------
extern "C" void kernel_launch(void* const* d_in, const int* in_sizes, int n_in,
                              void* d_out, int out_size) {
    const float* query  = (const float*)d_in[0];
    const float* values = (const float*)d_in[1];
    const float* W1     = (const float*)d_in[2];
    const float* W1b    = (const float*)d_in[3];
    const float* W2     = (const float*)d_in[4];
    const float* W2b    = (const float*)d_in[5];
    const float* Vk     = (const float*)d_in[6];
    const float* Vb     = (const float*)d_in[7];

    float* out = (float*)d_out;
    float* ctx = out;               // [B, D]
    float* wts = out + BB * DD;     // [B, T, 1]

    static bool attr_set = false;
    if (!attr_set) {
        cudaFuncSetAttribute(scores_kernel, cudaFuncAttributeMaxDynamicSharedMemorySize,
                             SMEM_BYTES);
        attr_set = true;
    }

    hq_kernel<<<BB, UU>>>(query, W2, W2b);
    prep_kernel<<<UU, DD>>>(W1);
    scores_kernel<<<NCTA, 256, SMEM_BYTES>>>(values, W1b, Vk, Vb);
    reduce_kernel<<<BB, DD>>>(ctx);
    weights_kernel<<<(BB * TT) / 256, 256>>>(wts);
}

// round 10
// speedup vs baseline: 2.5079x; 1.1948x over previous
#include <cuda_runtime.h>
#include <cuda_fp16.h>
#include <cstdint>

#define BB 32
#define TT 8192
#define DD 256
#define UU 128
#define MT 128
#define NCTA ((BB * TT) / MT)   // 2048 CTAs, 64 per batch

#define AROW 528                 // A row stride BYTES: 512 payload + 16 pad
// ---- dynamic SMEM layout (bytes) ----
#define A_OFF   0                // 128 rows x 528B = 67584 (full fp16 tile)
#define B_OFF   67584            // 4 x (128 rows x 80B) = 40960
#define SC_OFF  108544           // [2][128] floats = 1024
#define ES_OFF  109568           // 128 floats
#define HQ_OFF  110080           // 128 floats
#define B1_OFF  110592           // 128 floats
#define VV_OFF  111104           // 128 floats
#define RED_OFF 111616           // 64 floats
#define SMEM_BYTES 112128

// ---- scratch globals (allocation-free) ----
__device__ float  g_hq[BB * UU];
__device__ __half g_W1h[UU * DD];       // W1 transposed -> [u][d], fp16
__device__ float  g_scores[BB * TT];
__device__ float  g_stats[NCTA * 2];    // per-CTA (local max, local expsum)
__device__ float  g_pctx[NCTA * DD];    // per-CTA unnormalized partial context
__device__ float  g_bstats[BB * 2];     // per-batch (global max, 1/sum)

// ---------------------------------------------------------------------------
// helpers
// ---------------------------------------------------------------------------
__device__ __forceinline__ uint32_t smem_u32(const void* p) {
    uint32_t a;
    asm("{ .reg .u64 t; cvta.to.shared.u64 t, %1; cvt.u32.u64 %0, t; }" : "=r"(a) : "l"(p));
    return a;
}
__device__ __forceinline__ void ldsm4(uint32_t (&r)[4], uint32_t addr) {
    asm volatile("ldmatrix.sync.aligned.m8n8.x4.shared.b16 {%0,%1,%2,%3}, [%4];"
                 : "=r"(r[0]), "=r"(r[1]), "=r"(r[2]), "=r"(r[3]) : "r"(addr));
}
__device__ __forceinline__ void mma_f16(float c[4],
                                        uint32_t a0, uint32_t a1, uint32_t a2, uint32_t a3,
                                        uint32_t b0, uint32_t b1) {
    asm volatile(
        "mma.sync.aligned.m16n8k16.row.col.f32.f16.f16.f32 "
        "{%0,%1,%2,%3}, {%4,%5,%6,%7}, {%8,%9}, {%0,%1,%2,%3};"
        : "+f"(c[0]), "+f"(c[1]), "+f"(c[2]), "+f"(c[3])
        : "r"(a0), "r"(a1), "r"(a2), "r"(a3), "r"(b0), "r"(b1));
}
__device__ __forceinline__ void cp16(uint32_t dst, const void* src) {
    asm volatile("cp.async.cg.shared.global [%0], [%1], 16;"
                 :: "r"(dst), "l"(src) : "memory");
}
__device__ __forceinline__ void cp_commit() {
    asm volatile("cp.async.commit_group;" ::: "memory");
}
__device__ __forceinline__ void cp_wait2() {
    asm volatile("cp.async.wait_group 2;" ::: "memory");
}
__device__ __forceinline__ uint32_t h2_bits(__half2 h) {
    union { __half2 h; uint32_t u; } cvt;
    cvt.h = h;
    return cvt.u;
}
__device__ __forceinline__ float tanh_fast(float x) {   // 1 MUFU, ~5e-4 abs err
    float y;
    asm("tanh.approx.f32 %0, %1;" : "=f"(y) : "f"(x));
    return y;
}

// ---------------------------------------------------------------------------
// fused prep: blocks 0..31 -> hq, blocks 32..159 -> W1 transpose+fp16
// ---------------------------------------------------------------------------
__global__ void prep_kernel(const float* __restrict__ query,
                            const float* __restrict__ W2,
                            const float* __restrict__ W2b,
                            const float* __restrict__ W1) {
    if (blockIdx.x < 32) {
        if (threadIdx.x < UU) {
            int b = blockIdx.x, u = threadIdx.x;
            const float* q = query + b * DD;
            float acc = 0.0f;
#pragma unroll 8
            for (int d = 0; d < DD; d++) acc += q[d] * W2[d * UU + u];
            g_hq[b * UU + u] = fmaxf(acc + W2b[u], 0.0f);
        }
    } else {
        int u = blockIdx.x - 32, d = threadIdx.x;
        g_W1h[u * DD + d] = __float2half_rn(W1[d * UU + u]);
    }
}

// ---------------------------------------------------------------------------
// fused: scores (fp16 mma, persistent A tile, cp.async 4-ring B) + local
//        softmax + partial context (from SMEM fp16).  256 threads, 8 warps;
//        warp = (rg 0..3, ch 0..1): rows [32*rg,+32) x cols [64*ch,+64).
// ---------------------------------------------------------------------------
__global__ __launch_bounds__(256, 2)
void scores_kernel(const float* __restrict__ values,
                   const float* __restrict__ W1b,
                   const float* __restrict__ Vk,
                   const float* __restrict__ Vb) {
    extern __shared__ char smem[];
    const uint32_t sbase = smem_u32(smem);
    const int tid  = threadIdx.x;
    const int wid  = tid >> 5;
    const int lane = tid & 31;
    const int rg   = wid >> 1;
    const int ch   = wid & 1;
    const int mrow = lane & 7;
    const int mi   = lane >> 3;
    const int tg   = lane & 3;
    const int g    = lane >> 2;
    const int row0 = blockIdx.x * MT;
    const int b    = blockIdx.x >> 6;   // 64 CTAs per batch

    float* s_sc = (float*)(smem + SC_OFF);
    float* s_es = (float*)(smem + ES_OFF);
    float* s_hq = (float*)(smem + HQ_OFF);
    float* s_b1 = (float*)(smem + B1_OFF);
    float* s_v  = (float*)(smem + VV_OFF);
    float* s_rd = (float*)(smem + RED_OFF);

    if (tid < UU) {
        s_hq[tid] = g_hq[b * UU + tid];
        s_b1[tid] = W1b[tid];
        s_v[tid]  = Vk[tid];
    }

    // ---- B staging via cp.async (fp16, 4-buffer ring) ----
    auto stageB = [&](int c) {
        const uint32_t base = sbase + B_OFF + (c & 3) * 10240;
        const __half* src0 = g_W1h + c * 32;
#pragma unroll
        for (int i = 0; i < 2; i++) {
            int idx = tid + i * 256;         // 512 x 16B = 128 rows x 32 halves
            int u = idx >> 2, kk = idx & 3;
            cp16(base + u * 80 + kk * 16, src0 + u * DD + kk * 8);
        }
    };

    // ---- A staging: LDG fp32 -> regs -> cvt -> STS fp16 into chunk slice ----
    const int ar  = tid >> 3;                // base row handled by this thread
    const int ac4 = tid & 7;                 // float4 column within chunk
    float4 av[4];
    auto ldgA = [&](int c) {
        const float* src0 = values + (size_t)row0 * DD + c * 32 + ac4 * 4;
#pragma unroll
        for (int i = 0; i < 4; i++)
            av[i] = *(const float4*)(src0 + (size_t)(ar + i * 32) * DD);
    };
    auto stsA = [&](int c) {
#pragma unroll
        for (int i = 0; i < 4; i++) {
            __half2 h0 = __floats2half2_rn(av[i].x, av[i].y);
            __half2 h1 = __floats2half2_rn(av[i].z, av[i].w);
            uint2 u2 = make_uint2(h2_bits(h0), h2_bits(h1));
            *(uint2*)(smem + A_OFF + (ar + i * 32) * AROW + c * 64 + ac4 * 8) = u2;
        }
    };

    stageB(0); cp_commit();
    stageB(1); cp_commit();
    stageB(2); cp_commit();
    ldgA(0);
    stsA(0);
    ldgA(1);
    cp_wait2();
    __syncthreads();

    float acc[2][8][4];
#pragma unroll
    for (int m = 0; m < 2; m++)
#pragma unroll
        for (int j = 0; j < 8; j++)
#pragma unroll
            for (int q = 0; q < 4; q++) acc[m][j][q] = 0.0f;

    // fragment address components
    const int a_r  = 32 * rg + mrow + 8 * (mi & 1);
    const int a_kb = (mi >> 1) * 16;
    const int b_n  = 64 * ch + mrow + 8 * (mi >> 1);
    const int b_kb = (mi & 1) * 16;

    for (int c = 0; c < 8; c++) {
        const uint32_t abase = sbase + A_OFF + c * 64;
        const uint32_t bbase = sbase + B_OFF + (c & 3) * 10240;
#pragma unroll
        for (int ks = 0; ks < 2; ks++) {
            const int k0 = ks * 32;          // bytes within 64B chunk slice
            uint32_t a0[4], a1[4];
            ldsm4(a0, abase + (a_r)      * AROW + a_kb + k0);
            ldsm4(a1, abase + (a_r + 16) * AROW + a_kb + k0);
#pragma unroll
            for (int nt = 0; nt < 4; nt++) {
                uint32_t bq[4];
                ldsm4(bq, bbase + (b_n + 16 * nt) * 80 + b_kb + k0);
                mma_f16(acc[0][2 * nt],     a0[0], a0[1], a0[2], a0[3], bq[0], bq[1]);
                mma_f16(acc[0][2 * nt + 1], a0[0], a0[1], a0[2], a0[3], bq[2], bq[3]);
                mma_f16(acc[1][2 * nt],     a1[0], a1[1], a1[2], a1[3], bq[0], bq[1]);
                mma_f16(acc[1][2 * nt + 1], a1[0], a1[1], a1[2], a1[3], bq[2], bq[3]);
            }
        }
        if (c + 1 < 8) stsA(c + 1);
        if (c + 2 < 8) ldgA(c + 2);
        if (c + 3 < 8) stageB(c + 3);
        cp_commit();
        cp_wait2();
        __syncthreads();
    }

    // ---- epilogue 1: per-row score partials (this warp's 64-col half) ----
    float s[4] = {0.f, 0.f, 0.f, 0.f};
#pragma unroll
    for (int j = 0; j < 8; j++) {
        const int u0 = 64 * ch + 8 * j + 2 * tg;
        const int u1 = u0 + 1;
        const float v0 = s_v[u0], v1 = s_v[u1];
        const float h0 = s_hq[u0], h1 = s_hq[u1];
        const float c0 = s_b1[u0], c1 = s_b1[u1];
#pragma unroll
        for (int m = 0; m < 2; m++) {
            s[2 * m]     += v0 * tanh_fast(fmaxf(acc[m][j][0] + c0, 0.f) + h0)
                          + v1 * tanh_fast(fmaxf(acc[m][j][1] + c1, 0.f) + h1);
            s[2 * m + 1] += v0 * tanh_fast(fmaxf(acc[m][j][2] + c0, 0.f) + h0)
                          + v1 * tanh_fast(fmaxf(acc[m][j][3] + c1, 0.f) + h1);
        }
    }
#pragma unroll
    for (int i = 0; i < 4; i++) {
        s[i] += __shfl_xor_sync(0xffffffffu, s[i], 1);
        s[i] += __shfl_xor_sync(0xffffffffu, s[i], 2);
    }
    if (tg == 0) {
        const int rb = 32 * rg + g;
        s_sc[ch * 128 + rb]      = s[0];
        s_sc[ch * 128 + rb + 8]  = s[1];
        s_sc[ch * 128 + rb + 16] = s[2];
        s_sc[ch * 128 + rb + 24] = s[3];
    }
    __syncthreads();

    // ---- epilogue 2: combine halves, local max / exp / sum ----
    float myv = -3.0e38f;
    if (tid < 128) {
        myv = s_sc[tid] + s_sc[128 + tid] + Vb[0];
        g_scores[row0 + tid] = myv;
    }
    float m = myv;
#pragma unroll
    for (int o = 16; o > 0; o >>= 1) m = fmaxf(m, __shfl_xor_sync(0xffffffffu, m, o));
    if (lane == 0 && wid < 4) s_rd[wid] = m;
    __syncthreads();
    if (tid == 0) {
        s_rd[32] = fmaxf(fmaxf(s_rd[0], s_rd[1]), fmaxf(s_rd[2], s_rd[3]));
    }
    __syncthreads();
    const float mloc = s_rd[32];
    float e = (tid < 128) ? __expf(myv - mloc) : 0.0f;
    if (tid < 128) s_es[tid] = e;
    float sum = e;
#pragma unroll
    for (int o = 16; o > 0; o >>= 1) sum += __shfl_xor_sync(0xffffffffu, sum, o);
    if (lane == 0 && wid < 4) s_rd[8 + wid] = sum;
    __syncthreads();
    if (tid == 0) {
        g_stats[blockIdx.x * 2]     = mloc;
        g_stats[blockIdx.x * 2 + 1] = s_rd[8] + s_rd[9] + s_rd[10] + s_rd[11];
    }

    // ---- epilogue 3: partial context from the persistent SMEM fp16 A tile ----
    {
        float a = 0.0f;
#pragma unroll 8
        for (int r = 0; r < MT; r++) {
            __half hv = *(const __half*)(smem + A_OFF + r * AROW + tid * 2);
            a += s_es[r] * __half2float(hv);
        }
        g_pctx[blockIdx.x * DD + tid] = a;
    }
}

// ---------------------------------------------------------------------------
// per-batch rescale + context reduction (64 partials per batch), parallel
// ---------------------------------------------------------------------------
__global__ void reduce_kernel(float* __restrict__ ctx) {
    __shared__ float coef[64], red[8];
    const int b = blockIdx.x, tid = threadIdx.x, lane = tid & 31, w = tid >> 5;
    float val = 0.0f, cs = 0.0f;
    float m = -3.0e38f;
    if (tid < 64) {
        val = g_stats[(b * 64 + tid) * 2];
        cs  = g_stats[(b * 64 + tid) * 2 + 1];
        m = val;
    }
#pragma unroll
    for (int o = 16; o > 0; o >>= 1) m = fmaxf(m, __shfl_xor_sync(0xffffffffu, m, o));
    if (tid < 64 && lane == 0) red[w] = m;
    __syncthreads();
    if (tid == 0) red[2] = fmaxf(red[0], red[1]);
    __syncthreads();
    const float M = red[2];
    float c = 0.0f;
    if (tid < 64) {
        c = __expf(val - M);
        coef[tid] = c;
        c *= cs;
    }
#pragma unroll
    for (int o = 16; o > 0; o >>= 1) c += __shfl_xor_sync(0xffffffffu, c, o);
    if (tid < 64 && lane == 0) red[4 + w] = c;
    __syncthreads();
    if (tid == 0) {
        float S = red[4] + red[5];
        red[6] = 1.0f / S;
        g_bstats[b * 2] = M;
        g_bstats[b * 2 + 1] = 1.0f / S;
    }
    __syncthreads();
    const float inv = red[6];
    float acc = 0.0f;
#pragma unroll
    for (int k = 0; k < 64; k++) acc += coef[k] * g_pctx[(b * 64 + k) * DD + tid];
    ctx[b * DD + tid] = acc * inv;
}

// normalized attention weights
__global__ void weights_kernel(float* __restrict__ w) {
    int i = blockIdx.x * 256 + threadIdx.x;
    int b = i >> 13;
    w[i] = __expf(g_scores[i] - g_bstats[b * 2]) * g_bstats[b * 2 + 1];
}

// ---------------------------------------------------------------------------
extern "C" void kernel_launch(void* const* d_in, const int* in_sizes, int n_in,
                              void* d_out, int out_size) {
    const float* query  = (const float*)d_in[0];
    const float* values = (const float*)d_in[1];
    const float* W1     = (const float*)d_in[2];
    const float* W1b    = (const float*)d_in[3];
    const float* W2     = (const float*)d_in[4];
    const float* W2b    = (const float*)d_in[5];
    const float* Vk     = (const float*)d_in[6];
    const float* Vb     = (const float*)d_in[7];

    float* out = (float*)d_out;
    float* ctx = out;               // [B, D]
    float* wts = out + BB * DD;     // [B, T, 1]

    static bool attr_set = false;
    if (!attr_set) {
        cudaFuncSetAttribute(scores_kernel, cudaFuncAttributeMaxDynamicSharedMemorySize,
                             SMEM_BYTES);
        attr_set = true;
    }

    prep_kernel<<<160, 256>>>(query, W2, W2b, W1);
    scores_kernel<<<NCTA, 256, SMEM_BYTES>>>(values, W1b, Vk, Vb);
    reduce_kernel<<<BB, 256>>>(ctx);
    weights_kernel<<<(BB * TT) / 256, 256>>>(wts);
}